// round 12
// baseline (speedup 1.0000x reference)
#include <cuda_runtime.h>
#include <math.h>

typedef unsigned long long ull;

#define T_STEPS 2048
#define BATCH   32
#define DIM     512
#define NA      33554432u   // 2048*32*512

// ---------------------------------------------------------------------------
// Static device scratch (no allocations anywhere)
// ---------------------------------------------------------------------------
__device__ float g_Ai[NA];                 // x@Wi^T + 2bi          [row][j]
__device__ float g_Az[NA];                 // x@Wz^T + bz + bi      [row][j]
__device__ float g_Ao[NA];                 // x@Wo^T + bo + bi      [row][j]
__device__ float g_h[2][BATCH * DIM];      // hidden-state double buffer
__device__ unsigned int g_bar;             // monotonic grid barrier counter

// ---------------------------------------------------------------------------
// f32x2 helpers (packed fp32 pair in one 64-bit register; 2x FFMA throughput)
// ---------------------------------------------------------------------------
__device__ __forceinline__ ull pack2(float x, float y) {
    ull r; asm("mov.b64 %0,{%1,%2};" : "=l"(r) : "f"(x), "f"(y)); return r;
}
__device__ __forceinline__ void unpack2(ull v, float& x, float& y) {
    asm("mov.b64 {%0,%1},%2;" : "=f"(x), "=f"(y) : "l"(v));
}
__device__ __forceinline__ void fma2(ull& c, ull a, ull b) {
    asm("fma.rn.f32x2 %0,%1,%2,%0;" : "+l"(c) : "l"(a), "l"(b));
}

// ---------------------------------------------------------------------------
// Init: zero h[0] and the grid barrier (re-run on every graph replay)
// ---------------------------------------------------------------------------
__global__ void init_kernel() {
    int tid = blockIdx.x * blockDim.x + threadIdx.x;
    if (tid == 0) g_bar = 0u;
    for (int i = tid; i < BATCH * DIM; i += gridDim.x * blockDim.x)
        g_h[0][i] = 0.0f;
}

// ---------------------------------------------------------------------------
// Precompute GEMM:  C[row][n] = X[row][:] . W[n][:] + b1[n] + b2[n]
// M = 65536 rows, N = 512, K = 512.  Tile 128x128, BK = 16, 256 threads,
// 8x8 microtile with k-paired f32x2 accumulators. blockIdx.z selects gate.
// ---------------------------------------------------------------------------
#define KP 9   // SMEM row stride in ull (16 floats = 8 ull + 1 pad)

__global__ __launch_bounds__(256, 1) void gemm_pre(
    const float* __restrict__ X,
    const float* __restrict__ Wi, const float* __restrict__ Wz,
    const float* __restrict__ Wo,
    const float* __restrict__ bi, const float* __restrict__ bz,
    const float* __restrict__ bo)
{
    const int z = blockIdx.z;
    const float* W  = (z == 0) ? Wi : (z == 1) ? Wz : Wo;
    const float* b1 = (z == 0) ? bi : (z == 1) ? bz : bo;
    const float* b2 = bi;
    float* C = (z == 0) ? g_Ai : (z == 1) ? g_Az : g_Ao;

    __shared__ ull sX[128 * KP];
    __shared__ ull sW[128 * KP];

    const int tid  = threadIdx.x;
    const int r    = tid >> 1;        // 0..127 (tile row for staging)
    const int half = tid & 1;         // which 8-float half of the BK=16 slab
    const size_t xrow = (size_t)(blockIdx.x * 128 + r) * 512 + half * 8;
    const size_t wrow = (size_t)(blockIdx.y * 128 + r) * 512 + half * 8;

    const int m0 = (tid >> 4) * 8;
    const int n0 = (tid & 15) * 8;

    ull acc[8][8];
    #pragma unroll
    for (int i = 0; i < 8; ++i)
        #pragma unroll
        for (int j = 0; j < 8; ++j) acc[i][j] = 0ull;

    // register prefetch of tile kt=0
    float4 px0 = __ldg((const float4*)(X + xrow));
    float4 px1 = __ldg((const float4*)(X + xrow) + 1);
    float4 pw0 = __ldg((const float4*)(W + wrow));
    float4 pw1 = __ldg((const float4*)(W + wrow) + 1);

    for (int kt = 0; kt < 32; ++kt) {
        __syncthreads();
        ull* dx = &sX[r * KP + half * 4];
        dx[0] = pack2(px0.x, px0.y);  dx[1] = pack2(px0.z, px0.w);
        dx[2] = pack2(px1.x, px1.y);  dx[3] = pack2(px1.z, px1.w);
        ull* dw = &sW[r * KP + half * 4];
        dw[0] = pack2(pw0.x, pw0.y);  dw[1] = pack2(pw0.z, pw0.w);
        dw[2] = pack2(pw1.x, pw1.y);  dw[3] = pack2(pw1.z, pw1.w);
        __syncthreads();

        if (kt + 1 < 32) {  // prefetch next tile while computing this one
            const float4* xp = (const float4*)(X + xrow + (size_t)(kt + 1) * 16);
            const float4* wp = (const float4*)(W + wrow + (size_t)(kt + 1) * 16);
            px0 = __ldg(xp);  px1 = __ldg(xp + 1);
            pw0 = __ldg(wp);  pw1 = __ldg(wp + 1);
        }

        #pragma unroll
        for (int k2 = 0; k2 < 8; ++k2) {
            ull a[8], bb[8];
            #pragma unroll
            for (int i = 0; i < 8; ++i) a[i]  = sX[(m0 + i) * KP + k2];
            #pragma unroll
            for (int j = 0; j < 8; ++j) bb[j] = sW[(n0 + j) * KP + k2];
            #pragma unroll
            for (int i = 0; i < 8; ++i)
                #pragma unroll
                for (int j = 0; j < 8; ++j) fma2(acc[i][j], a[i], bb[j]);
        }
    }

    // epilogue: collapse k-pair halves, add biases, store coalesced
    float bias[8];
    #pragma unroll
    for (int j = 0; j < 8; ++j) {
        int n = blockIdx.y * 128 + n0 + j;
        bias[j] = __ldg(b1 + n) + __ldg(b2 + n);
    }
    #pragma unroll
    for (int i = 0; i < 8; ++i) {
        size_t row = (size_t)(blockIdx.x * 128 + m0 + i);
        float v[8];
        #pragma unroll
        for (int j = 0; j < 8; ++j) {
            float lo, hi; unpack2(acc[i][j], lo, hi);
            v[j] = lo + hi + bias[j];
        }
        float4* dst = (float4*)(C + row * 512 + blockIdx.y * 128 + n0);
        dst[0] = make_float4(v[0], v[1], v[2], v[3]);
        dst[1] = make_float4(v[4], v[5], v[6], v[7]);
    }
}

// ---------------------------------------------------------------------------
// Recurrence: 64 persistent CTAs (one wave), CTA owns 8 output columns.
// Per step: stage h into SMEM, warp-per-k-slice f32x2 dot, cross-warp
// reduce, gates, store h_next, global counter barrier.
// SMEM (ull): sH 32x257, sW 8x258, red 2048 floats.
// ---------------------------------------------------------------------------
#define REC_SMEM ((32 * 257 + 8 * 258 + 1024) * 8)   // 90496 bytes

__global__ __launch_bounds__(256, 1) void rec_kernel(const float* __restrict__ Wi)
{
    extern __shared__ ull sm[];
    ull*   sH  = sm;                       // h, k-pairs: [b][k2], stride 257
    ull*   sW  = sm + 32 * 257;            // Wi slice:   [jl][k2], stride 258
    float* red = (float*)(sm + 32 * 257 + 8 * 258);  // partials [warp][b*8+jl]

    const int tid  = threadIdx.x;
    const int j0   = blockIdx.x * 8;       // this CTA's output columns
    const int lane = tid & 31;
    const int w    = tid >> 5;             // warp id -> k-slice [64w, 64w+64)
    const int jp   = lane & 3;             // j-pair within the 8 columns
    const int bg   = lane >> 2;            // batch group (4 rows each)
    const int k2b  = w * 32;               // k2 base (k2 = k/2)
    const int gb   = tid >> 3;             // gate-phase batch row
    const int gj   = tid & 7;              // gate-phase column

    // Stage Wi rows j0..j0+7 once (512 floats = 256 ull each)
    const ull* Wi8 = (const ull*)Wi;
    #pragma unroll
    for (int c = 0; c < 8; ++c) {
        int li = c * 256 + tid;
        int jl = li >> 8, kk = li & 255;
        sW[jl * 258 + kk] = __ldg(Wi8 + (size_t)(j0 + jl) * 256 + kk);
    }

    for (int t = 0; t < T_STEPS; ++t) {
        // Prefetch gate pre-activations early (independent of h)
        size_t ar = ((size_t)(t * 32 + gb)) * 512 + j0 + gj;
        float ai = __ldg(&g_Ai[ar]);
        float az = __ldg(&g_Az[ar]);
        float ao = __ldg(&g_Ao[ar]);

        // Stage h (L1-bypass: buffer alternates, L1 could be stale)
        const float4* hsrc = (const float4*)g_h[t & 1];
        #pragma unroll
        for (int c = 0; c < 16; ++c) {
            int li = c * 256 + tid;        // float4 index 0..4095
            int b = li >> 7, q = li & 127; // 128 float4 per h row
            float4 f = __ldcg(hsrc + b * 128 + q);
            sH[b * 257 + q * 2 + 0] = pack2(f.x, f.y);
            sH[b * 257 + q * 2 + 1] = pack2(f.z, f.w);
        }
        __syncthreads();

        // f32x2 dot over this warp's k-slice; lane tile = 4b x 2j
        ull acc[4][2] = {};
        #pragma unroll 4
        for (int k2 = 0; k2 < 32; ++k2) {
            int kk = k2b + k2;
            ull w0 = sW[(2 * jp + 0) * 258 + kk];
            ull w1 = sW[(2 * jp + 1) * 258 + kk];
            #pragma unroll
            for (int i = 0; i < 4; ++i) {
                ull hh = sH[(bg * 4 + i) * 257 + kk];
                fma2(acc[i][0], hh, w0);
                fma2(acc[i][1], hh, w1);
            }
        }
        #pragma unroll
        for (int i = 0; i < 4; ++i)
            #pragma unroll
            for (int jj = 0; jj < 2; ++jj) {
                float lo, hi; unpack2(acc[i][jj], lo, hi);
                red[w * 256 + (bg * 4 + i) * 8 + 2 * jp + jj] = lo + hi;
            }
        __syncthreads();

        // Cross-warp reduce: hWi[b][j]
        float s = 0.0f;
        #pragma unroll
        for (int ww = 0; ww < 8; ++ww) s += red[ww * 256 + tid];

        // Gates (biases already folded into A arrays)
        float zi = 1.0f / (1.0f + __expf(-(ai + s)));
        float zz = 1.0f / (1.0f + __expf(-(az + s)));
        float zo = 1.0f / (1.0f + __expf(-(ao + s)));
        float hn = zo * tanhf(zi * zz);
        g_h[(t + 1) & 1][gb * 512 + j0 + gj] = hn;

        // Grid barrier (monotonic counter; all 64 CTAs co-resident)
        __threadfence();
        __syncthreads();
        if (tid == 0) {
            atomicAdd(&g_bar, 1u);
            unsigned int target = (unsigned int)(t + 1) * gridDim.x;
            while (*((volatile unsigned int*)&g_bar) < target) { }
        }
        __syncthreads();
    }
}

// ---------------------------------------------------------------------------
// Output: out[b][o] = h_final[b][:] . Wy[o][:] + by[o]   (final h in g_h[0])
// ---------------------------------------------------------------------------
__global__ void out_kernel(const float* __restrict__ Wy,
                           const float* __restrict__ by,
                           float* __restrict__ out)
{
    int gid = blockIdx.x * 256 + threadIdx.x;   // 0..16383
    int b = gid >> 9, o = gid & 511;
    const float* h  = g_h[0] + b * 512;
    const float* wr = Wy + (size_t)o * 512;
    float acc = 0.0f;
    #pragma unroll 8
    for (int k = 0; k < 512; ++k) acc += h[k] * wr[k];
    out[gid] = acc + __ldg(by + o);
}

// ---------------------------------------------------------------------------
// Launch
// ---------------------------------------------------------------------------
extern "C" void kernel_launch(void* const* d_in, const int* in_sizes, int n_in,
                              void* d_out, int out_size)
{
    const float* word = (const float*)d_in[0];
    // d_in[1]=Wf, d_in[2]=bf unused (dead in the reference)
    const float* Wi = (const float*)d_in[3];
    const float* bi = (const float*)d_in[4];
    const float* Wz = (const float*)d_in[5];
    const float* bz = (const float*)d_in[6];
    const float* Wo = (const float*)d_in[7];
    const float* bo = (const float*)d_in[8];
    const float* Wy = (const float*)d_in[9];
    const float* by = (const float*)d_in[10];
    float* out = (float*)d_out;

    cudaFuncSetAttribute(rec_kernel,
                         cudaFuncAttributeMaxDynamicSharedMemorySize, REC_SMEM);

    init_kernel<<<16, 256>>>();
    gemm_pre<<<dim3(512, 4, 3), 256>>>(word, Wi, Wz, Wo, bi, bz, bo);
    rec_kernel<<<64, 256, REC_SMEM>>>(Wi);
    out_kernel<<<64, 256>>>(Wy, by, out);
}

// round 13
// speedup vs baseline: 1.4473x; 1.4473x over previous
#include <cuda_runtime.h>
#include <math.h>

typedef unsigned long long ull;

#define T_STEPS 2048
#define BATCH   32
#define DIM     512
#define NA      33554432u     // 2048*32*512

#define NREC      64          // recurrence CTAs (one co-resident wave slice)
#define GEMM_CTAS 6144        // 512 row-chunks * 4 n-tiles * 3 gates
#define CHUNKS    512         // each chunk = 128 rows = 4 timesteps
#define TILES_PER_CHUNK 12

// ---------------------------------------------------------------------------
// Static device scratch (no allocations anywhere)
// ---------------------------------------------------------------------------
__device__ float g_Ai[NA];                 // x@Wi^T + 2bi          [t*32+b][j]
__device__ float g_Az[NA];                 // x@Wz^T + bz + bi
__device__ float g_Ao[NA];                 // x@Wo^T + bo + bi
__device__ float g_h[2][BATCH * DIM];      // hidden double buffer (h[0]=0 at launch)
__device__ unsigned int g_bar;             // monotonic step barrier
__device__ unsigned int g_bar2;            // completion counter (for state reset)
__device__ unsigned int g_done[CHUNKS];    // per-chunk gemm completion (target 12)

// ---------------------------------------------------------------------------
// f32x2 + relaxed-sync helpers
// ---------------------------------------------------------------------------
__device__ __forceinline__ ull pack2(float x, float y) {
    ull r; asm("mov.b64 %0,{%1,%2};" : "=l"(r) : "f"(x), "f"(y)); return r;
}
__device__ __forceinline__ void unpack2(ull v, float& x, float& y) {
    asm("mov.b64 {%0,%1},%2;" : "=f"(x), "=f"(y) : "l"(v));
}
__device__ __forceinline__ void fma2(ull& c, ull a, ull b) {
    asm("fma.rn.f32x2 %0,%1,%2,%0;" : "+l"(c) : "l"(a), "l"(b));
}
__device__ __forceinline__ void red_add(unsigned int* p, unsigned int v) {
    asm volatile("red.relaxed.gpu.global.add.u32 [%0], %1;" :: "l"(p), "r"(v) : "memory");
}
__device__ __forceinline__ unsigned int ld_rlx(const unsigned int* p) {
    unsigned int v;
    asm volatile("ld.relaxed.gpu.global.u32 %0, [%1];" : "=r"(v) : "l"(p) : "memory");
    return v;
}

// ---------------------------------------------------------------------------
// SMEM plan (one extern buffer, max of both roles)
//   rec : sH 32*258 ull | sW 8*258 ull | red 1024 ull          = 90752 B
//   gemm: sX 128*9 ull  | sW 128*9 ull                         = 18432 B
// ---------------------------------------------------------------------------
#define HS 258                       // sH row stride (ull) — 16B-aligned, conflict-free
#define MEGA_SMEM ((32 * HS + 8 * HS + 1024) * 8)
#define KP 9                         // gemm SMEM row stride (ull)

// ---------------------------------------------------------------------------
// GEMM role: one 128x128 tile of one gate.  Publishes g_done[chunk].
// ---------------------------------------------------------------------------
__device__ void gemm_role(
    ull* sm, int local,
    const float* __restrict__ X,
    const float* __restrict__ Wi, const float* __restrict__ Wz,
    const float* __restrict__ Wo,
    const float* __restrict__ bi, const float* __restrict__ bz,
    const float* __restrict__ bo)
{
    const int chunk = local / TILES_PER_CHUNK;     // row-tile: rows [chunk*128, +128)
    const int sub   = local % TILES_PER_CHUNK;
    const int z     = sub >> 2;                    // gate
    const int yt    = sub & 3;                     // n-tile

    const float* W  = (z == 0) ? Wi : (z == 1) ? Wz : Wo;
    const float* b1 = (z == 0) ? bi : (z == 1) ? bz : bo;
    float* C = (z == 0) ? g_Ai : (z == 1) ? g_Az : g_Ao;

    ull* sX = sm;
    ull* sW = sm + 128 * KP;

    const int tid  = threadIdx.x;
    const int r    = tid >> 1;
    const int half = tid & 1;
    const size_t xrow = (size_t)(chunk * 128 + r) * 512 + half * 8;
    const size_t wrow = (size_t)(yt * 128 + r) * 512 + half * 8;

    const int m0 = (tid >> 4) * 8;
    const int n0 = (tid & 15) * 8;

    ull acc[8][8];
    #pragma unroll
    for (int i = 0; i < 8; ++i)
        #pragma unroll
        for (int j = 0; j < 8; ++j) acc[i][j] = 0ull;

    float4 px0 = __ldg((const float4*)(X + xrow));
    float4 px1 = __ldg((const float4*)(X + xrow) + 1);
    float4 pw0 = __ldg((const float4*)(W + wrow));
    float4 pw1 = __ldg((const float4*)(W + wrow) + 1);

    for (int kt = 0; kt < 32; ++kt) {
        __syncthreads();
        ull* dx = &sX[r * KP + half * 4];
        dx[0] = pack2(px0.x, px0.y);  dx[1] = pack2(px0.z, px0.w);
        dx[2] = pack2(px1.x, px1.y);  dx[3] = pack2(px1.z, px1.w);
        ull* dw = &sW[r * KP + half * 4];
        dw[0] = pack2(pw0.x, pw0.y);  dw[1] = pack2(pw0.z, pw0.w);
        dw[2] = pack2(pw1.x, pw1.y);  dw[3] = pack2(pw1.z, pw1.w);
        __syncthreads();

        if (kt + 1 < 32) {
            const float4* xp = (const float4*)(X + xrow + (size_t)(kt + 1) * 16);
            const float4* wp = (const float4*)(W + wrow + (size_t)(kt + 1) * 16);
            px0 = __ldg(xp);  px1 = __ldg(xp + 1);
            pw0 = __ldg(wp);  pw1 = __ldg(wp + 1);
        }

        #pragma unroll
        for (int k2 = 0; k2 < 8; ++k2) {
            ull a[8], bb[8];
            #pragma unroll
            for (int i = 0; i < 8; ++i) a[i]  = sX[(m0 + i) * KP + k2];
            #pragma unroll
            for (int j = 0; j < 8; ++j) bb[j] = sW[(n0 + j) * KP + k2];
            #pragma unroll
            for (int i = 0; i < 8; ++i)
                #pragma unroll
                for (int j = 0; j < 8; ++j) fma2(acc[i][j], a[i], bb[j]);
        }
    }

    float bias[8];
    #pragma unroll
    for (int j = 0; j < 8; ++j) {
        int n = yt * 128 + n0 + j;
        bias[j] = __ldg(b1 + n) + __ldg(bi + n);   // b2 = bi always
    }
    #pragma unroll
    for (int i = 0; i < 8; ++i) {
        size_t row = (size_t)(chunk * 128 + m0 + i);
        float v[8];
        #pragma unroll
        for (int j = 0; j < 8; ++j) {
            float lo, hi; unpack2(acc[i][j], lo, hi);
            v[j] = lo + hi + bias[j];
        }
        float4* dst = (float4*)(C + row * 512 + yt * 128 + n0);
        dst[0] = make_float4(v[0], v[1], v[2], v[3]);
        dst[1] = make_float4(v[4], v[5], v[6], v[7]);
    }

    // release: all stores visible, then publish tile completion
    __threadfence();
    __syncthreads();
    if (tid == 0) red_add(&g_done[chunk], 1u);
}

// ---------------------------------------------------------------------------
// Recurrence role (blocks 0..63): consumes A chunks as they appear,
// then computes the output GEMM slice and resets state for the next replay.
// ---------------------------------------------------------------------------
__device__ void rec_role(
    ull* sm,
    const float* __restrict__ Wi,
    const float* __restrict__ Wy,
    const float* __restrict__ by,
    float* __restrict__ out)
{
    ull*   sH  = sm;                      // h k-pairs  [b][k2], stride HS
    ull*   sW  = sm + 32 * HS;            // Wi slice   [jl][k2], stride HS
    float* red = (float*)(sm + 40 * HS);  // partials   [warp][b*8 + j]
    ull*   redu = (ull*)red;

    const int tid  = threadIdx.x;
    const int j0   = blockIdx.x * 8;
    const int lane = tid & 31;
    const int w    = tid >> 5;            // warp -> k2 slice [32w, 32w+32)
    const int jp   = lane >> 3;           // j-pair (0..3)
    const int bg   = lane & 7;            // batch sub-row (conflict-free spread)
    const int k2b  = w * 32;
    const int gb   = tid >> 3;            // gate-phase batch row
    const int gj   = tid & 7;             // gate-phase column

    // Stage this CTA's 8 Wi rows once
    const ull* Wi8 = (const ull*)Wi;
    #pragma unroll
    for (int c = 0; c < 8; ++c) {
        int li = c * 256 + tid;
        int jl = li >> 8, kk = li & 255;
        sW[jl * HS + kk] = __ldg(Wi8 + (size_t)(j0 + jl) * 256 + kk);
    }

    for (int t = 0; t < T_STEPS; ++t) {
        // Wait for this timestep's pre-activations (every 4 steps)
        if ((t & 3) == 0) {
            if (tid == 0) {
                const unsigned int* f = &g_done[t >> 2];
                while (ld_rlx(f) < TILES_PER_CHUNK) { }
            }
            __syncthreads();
        }

        // Prefetch gate pre-activations (L2-hot thanks to overlap)
        size_t ar = ((size_t)(t * 32 + gb)) * 512 + j0 + gj;
        float ai = __ldcg(&g_Ai[ar]);
        float az = __ldcg(&g_Az[ar]);
        float ao = __ldcg(&g_Ao[ar]);

        // Stage h (L1-bypass; buffer alternates across steps)
        const float4* hsrc = (const float4*)g_h[t & 1];
        #pragma unroll
        for (int c = 0; c < 16; ++c) {
            int li = c * 256 + tid;        // float4 index == b*128 + q
            int b = li >> 7, q = li & 127;
            float4 f = __ldcg(hsrc + li);
            *(float4*)&sH[b * HS + q * 2] = f;   // already the 2 k-pair ulls
        }
        __syncthreads();

        // f32x2 dot over this warp's k2 slice; lane tile = 4b x 2j
        ull acc[4][2] = {};
        #pragma unroll 4
        for (int k2 = 0; k2 < 32; ++k2) {
            int kk = k2b + k2;
            ull w0 = sW[(2 * jp + 0) * HS + kk];
            ull w1 = sW[(2 * jp + 1) * HS + kk];
            #pragma unroll
            for (int i = 0; i < 4; ++i) {
                ull hh = sH[(bg + i * 8) * HS + kk];
                fma2(acc[i][0], hh, w0);
                fma2(acc[i][1], hh, w1);
            }
        }
        #pragma unroll
        for (int i = 0; i < 4; ++i) {
            int b = bg + i * 8;
            float l0, h0, l1, h1;
            unpack2(acc[i][0], l0, h0);
            unpack2(acc[i][1], l1, h1);
            redu[w * 128 + b * 4 + jp] = pack2(l0 + h0, l1 + h1);
        }
        __syncthreads();

        // Cross-warp reduce -> hWi[b][j]
        float s = 0.0f;
        #pragma unroll
        for (int ww = 0; ww < 8; ++ww) s += red[ww * 256 + tid];

        // Gates (all biases pre-folded into A arrays)
        float zi = 1.0f / (1.0f + __expf(-(ai + s)));
        float zz = 1.0f / (1.0f + __expf(-(az + s)));
        float zo = 1.0f / (1.0f + __expf(-(ao + s)));
        float hn = zo * tanhf(zi * zz);
        g_h[(t + 1) & 1][gb * 512 + j0 + gj] = hn;

        // Step barrier over the 64 rec CTAs
        __threadfence();
        __syncthreads();
        if (tid == 0) {
            red_add(&g_bar, 1u);
            const unsigned int tgt = (unsigned int)(t + 1) * NREC;
            while (ld_rlx(&g_bar) < tgt) { }
        }
        __syncthreads();
    }

    // ---- Epilogue: output GEMM on final h (lives in g_h[0]) ----
    const float4* hsrc = (const float4*)g_h[0];
    #pragma unroll
    for (int c = 0; c < 16; ++c) {
        int li = c * 256 + tid;
        int b = li >> 7, q = li & 127;
        float4 f = __ldcg(hsrc + li);
        *(float4*)&sH[b * HS + q * 2] = f;
    }
    __syncthreads();
    // barrier: everyone finished staging before anyone zeroes h for next replay
    if (tid == 0) {
        red_add(&g_bar, 1u);
        while (ld_rlx(&g_bar) < (unsigned int)(T_STEPS + 1) * NREC) { }
    }
    __syncthreads();

    // zero own h columns (next replay needs h0 = 0)
    g_h[0][gb * 512 + j0 + gj] = 0.0f;

    // out[b][j0+gj] = h[b][:] . Wy[j0+gj][:] + by
    const ull* wy2 = (const ull*)(Wy + (size_t)(j0 + gj) * 512);
    ull oacc = 0ull;
    #pragma unroll 8
    for (int k2 = 0; k2 < 256; ++k2)
        fma2(oacc, sH[gb * HS + k2], __ldg(wy2 + k2));
    float lo, hi; unpack2(oacc, lo, hi);
    out[gb * 512 + j0 + gj] = lo + hi + __ldg(by + j0 + gj);

    // ---- completion + state reset for the next graph replay ----
    __threadfence();
    __syncthreads();
    if (tid == 0) red_add(&g_bar2, 1u);
    if (blockIdx.x == 0 && tid == 0) {
        while (ld_rlx(&g_bar2) < NREC) { }
        g_bar = 0u;
        for (int i = 0; i < CHUNKS; ++i) g_done[i] = 0u;
        __threadfence();
        g_bar2 = 0u;
    }
}

// ---------------------------------------------------------------------------
// Fused persistent kernel
// ---------------------------------------------------------------------------
__global__ __launch_bounds__(256, 1) void mega_kernel(
    const float* __restrict__ word,
    const float* __restrict__ Wi, const float* __restrict__ bi,
    const float* __restrict__ Wz, const float* __restrict__ bz,
    const float* __restrict__ Wo, const float* __restrict__ bo,
    const float* __restrict__ Wy, const float* __restrict__ by,
    float* __restrict__ out)
{
    extern __shared__ ull sm[];
    if (blockIdx.x < NREC) {
        rec_role(sm, Wi, Wy, by, out);
    } else {
        gemm_role(sm, blockIdx.x - NREC, word, Wi, Wz, Wo, bi, bz, bo);
    }
}

// ---------------------------------------------------------------------------
// Launch (single graph node)
// ---------------------------------------------------------------------------
extern "C" void kernel_launch(void* const* d_in, const int* in_sizes, int n_in,
                              void* d_out, int out_size)
{
    const float* word = (const float*)d_in[0];
    // d_in[1]=Wf, d_in[2]=bf are dead in the reference
    const float* Wi = (const float*)d_in[3];
    const float* bi = (const float*)d_in[4];
    const float* Wz = (const float*)d_in[5];
    const float* bz = (const float*)d_in[6];
    const float* Wo = (const float*)d_in[7];
    const float* bo = (const float*)d_in[8];
    const float* Wy = (const float*)d_in[9];
    const float* by = (const float*)d_in[10];
    float* out = (float*)d_out;

    cudaFuncSetAttribute(mega_kernel,
                         cudaFuncAttributeMaxDynamicSharedMemorySize, MEGA_SMEM);

    mega_kernel<<<NREC + GEMM_CTAS, 256, MEGA_SMEM>>>(
        word, Wi, bi, Wz, bz, Wo, bo, Wy, by, out);
}